// round 17
// baseline (speedup 1.0000x reference)
#include <cuda_runtime.h>
#include <cuda_fp16.h>
#include <cooperative_groups.h>
namespace cg = cooperative_groups;

#define NN   50000
#define EE   800000
#define HID  64
#define IND  128
#define OUTD 40
#define NBLK ((NN + 255) / 256)   // 196 scan chunks
#define GB   ((NN + 63) / 64)     // 782 gemm tiles
#define WTOT (IND*64 + HID*64 + HID*64 + 192*64)
#define SMEM_BYTES 36864          // max(gemm1 35840, final 36864)

// ---------------- device scratch ----------------
__device__ __half g_hlin[NN * HID];
__device__ __half g_h0[NN * HID];
__device__ __half g_h1[NN * HID];
__device__ __half g_h2[NN * HID];
__device__ __half g_w1[IND * 64];
__device__ __half g_w2[HID * 64];
__device__ __half g_w3[HID * 64];
__device__ __half g_wl[192 * 64];
__device__ int   g_rowptr[NN + 1];
__device__ int   g_cnt[NN];
__device__ int   g_agg[NBLK];
__device__ int   g_flag[NBLK];
__device__ int4  g_edge4[EE / 2];
__device__ int   g_is64;

__device__ __forceinline__ int clampN(int v) {
    return (v < 0) ? 0 : ((v >= NN) ? NN - 1 : v);
}
__device__ __forceinline__ int edge_at(const int* __restrict__ p32, int row, int e, int is64) {
    long long idx = (long long)row * EE + e;
    return is64 ? p32[2 * idx] : p32[idx];
}
__device__ __forceinline__ unsigned smem_u32(const void* p) {
    return (unsigned)__cvta_generic_to_shared(p);
}
__device__ __forceinline__ void ldm_x4(unsigned& r0, unsigned& r1, unsigned& r2, unsigned& r3, unsigned a) {
    asm volatile("ldmatrix.sync.aligned.m8n8.x4.shared.b16 {%0,%1,%2,%3}, [%4];"
                 : "=r"(r0), "=r"(r1), "=r"(r2), "=r"(r3) : "r"(a));
}
__device__ __forceinline__ void ldm_x4_t(unsigned& r0, unsigned& r1, unsigned& r2, unsigned& r3, unsigned a) {
    asm volatile("ldmatrix.sync.aligned.m8n8.x4.trans.shared.b16 {%0,%1,%2,%3}, [%4];"
                 : "=r"(r0), "=r"(r1), "=r"(r2), "=r"(r3) : "r"(a));
}
__device__ __forceinline__ void mma16816(float* c, unsigned a0, unsigned a1, unsigned a2, unsigned a3,
                                         unsigned b0, unsigned b1) {
    asm volatile("mma.sync.aligned.m16n8k16.row.col.f32.f16.f16.f32 "
                 "{%0,%1,%2,%3}, {%4,%5,%6,%7}, {%8,%9}, {%0,%1,%2,%3};"
                 : "+f"(c[0]), "+f"(c[1]), "+f"(c[2]), "+f"(c[3])
                 : "r"(a0), "r"(a1), "r"(a2), "r"(a3), "r"(b0), "r"(b1));
}

// block-wide exclusive scan over 256 threads; wsum[7] = block total afterwards
__device__ __forceinline__ int block_excl_scan_256(int v, int tid, int* wsum) {
    int lane = tid & 31, w = tid >> 5;
    int x = v;
#pragma unroll
    for (int o = 1; o < 32; o <<= 1) {
        int y = __shfl_up_sync(0xFFFFFFFFu, x, o);
        if (lane >= o) x += y;
    }
    if (lane == 31) wsum[w] = x;
    __syncthreads();
    if (w == 0) {
        int s = (lane < 8) ? wsum[lane] : 0;
#pragma unroll
        for (int o = 1; o < 8; o <<= 1) {
            int y = __shfl_up_sync(0xFFFFFFFFu, s, o);
            if (lane >= o) s += y;
        }
        if (lane < 8) wsum[lane] = s;
    }
    __syncthreads();
    int incl = x + ((w > 0) ? wsum[w - 1] : 0);
    return incl - v;
}

// per-node aggregation (lane owns one half2 column); returns relu(sum + bias)
__device__ __forceinline__ __half2 agg_node(const __half2* __restrict__ hl,
                                            int node, int lane, float b0, float b1) {
    const int2* ed = (const int2*)g_edge4;
    int beg = g_rowptr[node], end = g_rowptr[node + 1];
    float a0 = 0.f, a1 = 0.f, c0 = 0.f, c1 = 0.f;
    int e = beg;
    if ((e & 1) && e < end) {
        int2 E = ed[e];
        float2 h = __half22float2(hl[(size_t)E.x * 32 + lane]);
        float w = __int_as_float(E.y);
        a0 = fmaf(w, h.x, a0); a1 = fmaf(w, h.y, a1);
        e++;
    }
    for (; e + 4 <= end; e += 4) {
        int4 Ea = g_edge4[e >> 1];
        int4 Eb = g_edge4[(e >> 1) + 1];
        float2 h0 = __half22float2(hl[(size_t)Ea.x * 32 + lane]);
        float2 h1 = __half22float2(hl[(size_t)Ea.z * 32 + lane]);
        float2 h2 = __half22float2(hl[(size_t)Eb.x * 32 + lane]);
        float2 h3 = __half22float2(hl[(size_t)Eb.z * 32 + lane]);
        float w0 = __int_as_float(Ea.y), w1 = __int_as_float(Ea.w);
        float w2 = __int_as_float(Eb.y), w3 = __int_as_float(Eb.w);
        a0 = fmaf(w0, h0.x, a0); a1 = fmaf(w0, h0.y, a1);
        c0 = fmaf(w1, h1.x, c0); c1 = fmaf(w1, h1.y, c1);
        a0 = fmaf(w2, h2.x, a0); a1 = fmaf(w2, h2.y, a1);
        c0 = fmaf(w3, h3.x, c0); c1 = fmaf(w3, h3.y, c1);
    }
    if (e + 2 <= end) {
        int4 Ea = g_edge4[e >> 1];
        float2 h0 = __half22float2(hl[(size_t)Ea.x * 32 + lane]);
        float2 h1 = __half22float2(hl[(size_t)Ea.z * 32 + lane]);
        float w0 = __int_as_float(Ea.y), w1 = __int_as_float(Ea.w);
        a0 = fmaf(w0, h0.x, a0); a1 = fmaf(w0, h0.y, a1);
        c0 = fmaf(w1, h1.x, c0); c1 = fmaf(w1, h1.y, c1);
        e += 2;
    }
    if (e < end) {
        int2 E = ed[e];
        float2 h = __half22float2(hl[(size_t)E.x * 32 + lane]);
        float w = __int_as_float(E.y);
        a0 = fmaf(w, h.x, a0); a1 = fmaf(w, h.y, a1);
    }
    a0 += c0; a1 += c1;
    return __floats2half2_rn(fmaxf(a0 + b0, 0.f), fmaxf(a1 + b1, 0.f));
}

// 64x64 mma tile, 8 warps (warp tile 16x32). Xs stride XSs halves, Ws stride 72.
// K16 steps = K/16. wsOff = column offset into Ws rows (for final's segments it's row offset handled by caller).
__device__ __forceinline__ void mma_tile64(const __half* Xs, int XSs, const __half* Ws,
                                           int k16, int warp, int lane, float acc[4][4]) {
    int wm = (warp & 3) * 16, wn = (warp >> 2) * 32;
    unsigned xb = smem_u32(Xs), wb = smem_u32(Ws);
    int arow = wm + ((lane >> 3) & 1) * 8 + (lane & 7);
    int acol8 = (lane >> 4) * 8;
    int brow8 = ((lane >> 3) & 1) * 8 + (lane & 7);
    for (int kk = 0; kk < k16; kk++) {
        unsigned a0, a1, a2, a3;
        ldm_x4(a0, a1, a2, a3, xb + (arow * XSs + kk * 16 + acol8) * 2);
#pragma unroll
        for (int jn = 0; jn < 2; jn++) {
            unsigned b0, b1, b2, b3;
            ldm_x4_t(b0, b1, b2, b3, wb + ((kk * 16 + brow8) * 72 + wn + jn * 16 + acol8) * 2);
            mma16816(acc[jn * 2 + 0], a0, a1, a2, a3, b0, b1);
            mma16816(acc[jn * 2 + 1], a0, a1, a2, a3, b2, b3);
        }
    }
}

// ---------------- THE megakernel ----------------
__global__ void __launch_bounds__(256, 4)
mega_kernel(const float* __restrict__ x,
            const int* __restrict__ ei32,
            const float* __restrict__ ew,
            const float* __restrict__ W1, const float* __restrict__ b1,
            const float* __restrict__ W2, const float* __restrict__ b2,
            const float* __restrict__ W3, const float* __restrict__ b3,
            const float* __restrict__ Wl, const float* __restrict__ bl,
            float* __restrict__ out) {
    cg::grid_group grid = cg::this_grid();
    extern __shared__ __half dsm[];
    __shared__ int wsum[8];
    __shared__ int s_off;

    int tid = threadIdx.x, warp = tid >> 5, lane = tid & 31;
    int gtid = blockIdx.x * 256 + tid;
    int gstride = gridDim.x * 256;

    // ---- P0: zero counters/flags, convert weights, detect dtype ----
    for (int i = gtid; i < NN; i += gstride) g_cnt[i] = 0;
    for (int i = gtid; i < NBLK; i += gstride) g_flag[i] = 0;
    for (int i = gtid; i < WTOT; i += gstride) {
        int j = i;
        if (j < IND * 64) { g_w1[j] = __float2half_rn(W1[j]); }
        else {
            j -= IND * 64;
            if (j < HID * 64) { g_w2[j] = __float2half_rn(W2[j]); }
            else {
                j -= HID * 64;
                if (j < HID * 64) { g_w3[j] = __float2half_rn(W3[j]); }
                else {
                    j -= HID * 64;
                    int k = j >> 6, c = j & 63;
                    g_wl[j] = (c < OUTD) ? __float2half_rn(Wl[k * OUTD + c]) : __float2half_rn(0.f);
                }
            }
        }
    }
    if (blockIdx.x == 0 && tid < 32) {
        int any = ei32[2 * tid + 1] | ei32[2 * (tid + 32) + 1];
        unsigned nz = __ballot_sync(0xFFFFFFFFu, any != 0);
        if (tid == 0) g_is64 = (nz == 0) ? 1 : 0;
    }
    grid.sync();

    // ---- P1: histogram ----
    int is64 = g_is64;
    for (int e = gtid; e < EE; e += gstride) {
        int d = clampN(edge_at(ei32, 1, e, is64));
        atomicAdd(&g_cnt[d], 1);
    }
    grid.sync();

    // ---- P2: single-pass lookback scan (blocks [0, NBLK)) ----
    if (blockIdx.x < NBLK) {
        int b = blockIdx.x;
        int i = b * 256 + tid;
        int c = (i < NN) ? g_cnt[i] : 0;
        int excl = block_excl_scan_256(c, tid, wsum);
        int total = wsum[7];
        if (tid == 0) {
            g_agg[b] = total;
            __threadfence();
            *(volatile int*)&g_flag[b] = 1;
        }
        if (tid < 32) {
            int sum = 0;
            for (int p = tid; p < b; p += 32) {
                while (*(volatile int*)&g_flag[p] == 0) { }
                sum += *(volatile int*)&g_agg[p];
            }
#pragma unroll
            for (int o = 16; o > 0; o >>= 1) sum += __shfl_down_sync(0xFFFFFFFFu, sum, o);
            if (tid == 0) s_off = sum;
        }
        __syncthreads();
        int off = s_off;
        if (i < NN) {
            g_rowptr[i] = off + excl;
            g_cnt[i] = 0;   // reset cursors for fill
        }
        if (b == NBLK - 1 && tid == 0) g_rowptr[NN] = off + total;
    }
    grid.sync();

    // ---- P3: fill ----
    for (int e = gtid; e < EE; e += gstride) {
        int d = clampN(edge_at(ei32, 1, e, is64));
        int s = clampN(edge_at(ei32, 0, e, is64));
        int pos = g_rowptr[d] + atomicAdd(&g_cnt[d], 1);
        ((int2*)g_edge4)[pos] = make_int2(s, __float_as_int(ew[e]));
    }
    grid.sync();

    // ---- P4: gemm1  hlin = fp16(x) @ W1 ----
    {
        __half* Xs = dsm;                 // 64 x 136
        __half* Ws = dsm + 64 * 136;      // 128 x 72
        for (int t = blockIdx.x; t < GB; t += gridDim.x) {
            __syncthreads();
            int row0 = t * 64;
            for (int i = tid; i < 64 * 32; i += 256) {     // 32 float4 per row
                int r = i >> 5, c = i & 31;
                int gr = row0 + r; if (gr >= NN) gr = NN - 1;
                float4 v = *(const float4*)&x[(size_t)gr * IND + c * 4];
                __half2 h01 = __floats2half2_rn(v.x, v.y);
                __half2 h23 = __floats2half2_rn(v.z, v.w);
                uint2 pk; pk.x = *(unsigned*)&h01; pk.y = *(unsigned*)&h23;
                *(uint2*)&Xs[r * 136 + c * 4] = pk;
            }
            for (int i = tid; i < IND * 8; i += 256) {
                int r = i >> 3, c = i & 7;
                *(uint4*)&Ws[r * 72 + c * 8] = *(const uint4*)&g_w1[r * 64 + c * 8];
            }
            __syncthreads();

            float acc[4][4];
#pragma unroll
            for (int g = 0; g < 4; g++) { acc[g][0] = acc[g][1] = acc[g][2] = acc[g][3] = 0.f; }
            mma_tile64(Xs, 136, Ws, IND / 16, warp, lane, acc);

            __half2* hl = (__half2*)g_hlin;
            int wm = (warp & 3) * 16, wn = (warp >> 2) * 32;
            int g = lane >> 2, q = lane & 3;
#pragma unroll
            for (int gn = 0; gn < 4; gn++) {
                int r0 = row0 + wm + g, r1 = r0 + 8;
                int cidx = (wn >> 1) + gn * 4 + q;
                if (r0 < NN) hl[(size_t)r0 * 32 + cidx] = __floats2half2_rn(acc[gn][0], acc[gn][1]);
                if (r1 < NN) hl[(size_t)r1 * 32 + cidx] = __floats2half2_rn(acc[gn][2], acc[gn][3]);
            }
        }
    }
    grid.sync();

    // ---- layers: agg -> gemm -> agg -> gemm -> agg ----
#pragma unroll 1
    for (int layer = 0; layer < 3; layer++) {
        // agg: hlin -> h{layer}
        const float* bias = (layer == 0) ? b1 : (layer == 1) ? b2 : b3;
        __half2* hout = (__half2*)((layer == 0) ? g_h0 : (layer == 1) ? g_h1 : g_h2);
        float bb0 = bias[lane * 2], bb1 = bias[lane * 2 + 1];
        for (int n = blockIdx.x * 8 + warp; n < NN; n += gridDim.x * 8) {
            hout[(size_t)n * 32 + lane] = agg_node((const __half2*)g_hlin, n, lane, bb0, bb1);
        }
        grid.sync();

        if (layer < 2) {
            // gemm: h{layer} @ W{layer+2} -> hlin
            const __half* H = (layer == 0) ? g_h0 : g_h1;
            const __half* Wp = (layer == 0) ? g_w2 : g_w3;
            __half* Xs = dsm;              // 64 x 72
            __half* Ws = dsm + 64 * 72;    // 64 x 72
            for (int t = blockIdx.x; t < GB; t += gridDim.x) {
                __syncthreads();
                int row0 = t * 64;
                for (int i = tid; i < 64 * 8; i += 256) {
                    int r = i >> 3, c = i & 7;
                    int gr = row0 + r; if (gr >= NN) gr = NN - 1;
                    *(uint4*)&Xs[r * 72 + c * 8] = *(const uint4*)&H[(size_t)gr * 64 + c * 8];
                }
                for (int i = tid; i < HID * 8; i += 256) {
                    int r = i >> 3, c = i & 7;
                    *(uint4*)&Ws[r * 72 + c * 8] = *(const uint4*)&Wp[r * 64 + c * 8];
                }
                __syncthreads();

                float acc[4][4];
#pragma unroll
                for (int g = 0; g < 4; g++) { acc[g][0] = acc[g][1] = acc[g][2] = acc[g][3] = 0.f; }
                mma_tile64(Xs, 72, Ws, HID / 16, warp, lane, acc);

                __half2* hl = (__half2*)g_hlin;
                int wm = (warp & 3) * 16, wn = (warp >> 2) * 32;
                int g = lane >> 2, q = lane & 3;
#pragma unroll
                for (int gn = 0; gn < 4; gn++) {
                    int r0 = row0 + wm + g, r1 = r0 + 8;
                    int cidx = (wn >> 1) + gn * 4 + q;
                    if (r0 < NN) hl[(size_t)r0 * 32 + cidx] = __floats2half2_rn(acc[gn][0], acc[gn][1]);
                    if (r1 < NN) hl[(size_t)r1 * 32 + cidx] = __floats2half2_rn(acc[gn][2], acc[gn][3]);
                }
            }
            grid.sync();
        }
    }

    // ---- P10: final  out = [h0|h1|h2] @ Wlpad + bl ----
    {
        __half* Xs = dsm;               // 64 x 72
        __half* Ws = dsm + 64 * 72;     // 192 x 72
        for (int i = tid; i < 192 * 8; i += 256) {
            int r = i >> 3, c = i & 7;
            *(uint4*)&Ws[r * 72 + c * 8] = *(const uint4*)&g_wl[r * 64 + c * 8];
        }
        for (int t = blockIdx.x; t < GB; t += gridDim.x) {
            int row0 = t * 64;
            float acc[4][4];
#pragma unroll
            for (int g = 0; g < 4; g++) { acc[g][0] = acc[g][1] = acc[g][2] = acc[g][3] = 0.f; }

#pragma unroll 1
            for (int l = 0; l < 3; l++) {
                const __half* H = (l == 0) ? g_h0 : (l == 1) ? g_h1 : g_h2;
                __syncthreads();
                for (int i = tid; i < 64 * 8; i += 256) {
                    int r = i >> 3, c = i & 7;
                    int gr = row0 + r; if (gr >= NN) gr = NN - 1;
                    *(uint4*)&Xs[r * 72 + c * 8] = *(const uint4*)&H[(size_t)gr * 64 + c * 8];
                }
                __syncthreads();
                mma_tile64(Xs, 72, Ws + l * 64 * 72, HID / 16, warp, lane, acc);
            }

            int wm = (warp & 3) * 16, wn = (warp >> 2) * 32;
            int g = lane >> 2, q = lane & 3;
#pragma unroll
            for (int gn = 0; gn < 4; gn++) {
                int col = wn + gn * 8 + q * 2;
                if (col >= OUTD) continue;
                float o0 = bl[col], o1 = bl[col + 1];
                int r0 = row0 + wm + g, r1 = r0 + 8;
                if (r0 < NN) {
                    float2 o; o.x = acc[gn][0] + o0; o.y = acc[gn][1] + o1;
                    *(float2*)&out[(size_t)r0 * OUTD + col] = o;
                }
                if (r1 < NN) {
                    float2 o; o.x = acc[gn][2] + o0; o.y = acc[gn][3] + o1;
                    *(float2*)&out[(size_t)r1 * OUTD + col] = o;
                }
            }
        }
    }
}

// ---------------- launch: one cooperative kernel ----------------
extern "C" void kernel_launch(void* const* d_in, const int* in_sizes, int n_in,
                              void* d_out, int out_size) {
    const float* x    = (const float*)d_in[0];
    const int*   ei32 = (const int*)d_in[1];
    const float* ew   = (const float*)d_in[2];
    const float* W1 = (const float*)d_in[3];
    const float* b1 = (const float*)d_in[4];
    const float* W2 = (const float*)d_in[5];
    const float* b2 = (const float*)d_in[6];
    const float* W3 = (const float*)d_in[7];
    const float* b3 = (const float*)d_in[8];
    const float* Wl = (const float*)d_in[9];
    const float* bl = (const float*)d_in[10];
    float* out = (float*)d_out;

    static int grid_sz = 0;
    if (!grid_sz) {
        cudaFuncSetAttribute(mega_kernel, cudaFuncAttributeMaxDynamicSharedMemorySize, SMEM_BYTES);
        int nb = 0, nsm = 0;
        cudaOccupancyMaxActiveBlocksPerMultiprocessor(&nb, (const void*)mega_kernel, 256, SMEM_BYTES);
        cudaDeviceGetAttribute(&nsm, cudaDevAttrMultiProcessorCount, 0);
        grid_sz = nb * nsm;
        if (grid_sz < NBLK) grid_sz = NBLK;   // scan requires >= NBLK resident blocks
    }

    void* args[] = { (void*)&x, (void*)&ei32, (void*)&ew,
                     (void*)&W1, (void*)&b1, (void*)&W2, (void*)&b2,
                     (void*)&W3, (void*)&b3, (void*)&Wl, (void*)&bl, (void*)&out };
    cudaLaunchCooperativeKernel((const void*)mega_kernel, dim3(grid_sz), dim3(256),
                                args, SMEM_BYTES, 0);
}